// round 14
// baseline (speedup 1.0000x reference)
#include <cuda_runtime.h>
#include <cuda_bf16.h>
#include <cstdint>
#include <math.h>

#define T_STEPS 2048
#define BATCH   64
#define EDIM    256
#define HDIM    256
#define G4      1024
#define VOCAB   50257
#define TBsz    (T_STEPS*BATCH)

typedef unsigned long long ull;

// ---------------- device scratch (no cudaMalloc allowed) ----------------
__device__ float d_P[(size_t)VOCAB * G4];   // projected embedding table, permuted cols

// permutation: j = g*256 + k, k = r*32+u  ->  pj = r*128 + g*32 + u
__device__ __forceinline__ int permj(int j) {
    int g = j >> 8; int k = j & 255; int r = k >> 5; int u = k & 31;
    return r * 128 + g * 32 + u;
}

__device__ __forceinline__ ull pack2(float a, float b) {
    ull r; asm("mov.b64 %0, {%1, %2};" : "=l"(r) : "f"(a), "f"(b)); return r;
}
__device__ __forceinline__ void fma2(ull& d, ull a, ull b) {
    asm("fma.rn.f32x2 %0, %1, %2, %0;" : "+l"(d) : "l"(a), "l"(b));
}
union F2 { ull u; float2 f; };

// ---------------- kernel 1: P = emb @ W_ih^T (NT gemm), permuted cols, f32x2 ----------------
#define BM 128
#define BN 128
#define BK 32
__global__ void __launch_bounds__(256)
proj_kernel(const float* __restrict__ emb, const float* __restrict__ Wih) {
    __shared__ float As[BK][BM + 1];
    __shared__ float Bs[BK][BN + 1];
    int l  = threadIdx.x;
    int v0 = blockIdx.x * BM;
    int j0 = blockIdx.y * BN;
    int ty = l >> 4, tx = l & 15;

    ull acc2[8][4];
#pragma unroll
    for (int i = 0; i < 8; i++)
#pragma unroll
        for (int j = 0; j < 4; j++) acc2[i][j] = 0ull;

    for (int kt = 0; kt < EDIM; kt += BK) {
        for (int idx = l; idx < BM * BK; idx += 256) {
            int vr = idx >> 5; int e = idx & 31;
            int v = v0 + vr;
            As[e][vr] = (v < VOCAB) ? emb[v * EDIM + kt + e] : 0.f;
        }
        for (int idx = l; idx < BN * BK; idx += 256) {
            int jr = idx >> 5; int e = idx & 31;
            Bs[e][jr] = Wih[(j0 + jr) * EDIM + kt + e];
        }
        __syncthreads();
#pragma unroll
        for (int kk = 0; kk < BK; kk++) {
            float a[8], b[8];
#pragma unroll
            for (int i = 0; i < 8; i++) a[i] = As[kk][ty * 8 + i];
#pragma unroll
            for (int i = 0; i < 8; i++) b[i] = Bs[kk][tx * 8 + i];
            ull pa[8], pb[4];
#pragma unroll
            for (int i = 0; i < 8; i++) pa[i] = pack2(a[i], a[i]);
#pragma unroll
            for (int j = 0; j < 4; j++) pb[j] = pack2(b[2 * j], b[2 * j + 1]);
#pragma unroll
            for (int i = 0; i < 8; i++)
#pragma unroll
                for (int j = 0; j < 4; j++) fma2(acc2[i][j], pa[i], pb[j]);
        }
        __syncthreads();
    }
    int jb  = j0 + tx * 8;
    int pj0 = permj(jb);
#pragma unroll
    for (int i = 0; i < 8; i++) {
        int v = v0 + ty * 8 + i;
        if (v < VOCAB) {
#pragma unroll
            for (int j = 0; j < 4; j++) {
                F2 x; x.u = acc2[i][j];
                d_P[(size_t)v * G4 + pj0 + 2 * j]     = x.f.x;
                d_P[(size_t)v * G4 + pj0 + 2 * j + 1] = x.f.y;
            }
        }
    }
}

// ---------------- kernel 2: persistent cluster LSTM + fused compaction ----------------
__device__ __forceinline__ void cluster_sync_() {
    asm volatile("barrier.cluster.arrive.aligned;" ::: "memory");
    asm volatile("barrier.cluster.wait.aligned;" ::: "memory");
}
__device__ __forceinline__ float sigf(float x) {
    return __fdividef(1.f, 1.f + __expf(-x));
}
__device__ __forceinline__ float tanhfast(float x) {
    return 1.f - 2.f * __fdividef(1.f, __expf(2.f * x) + 1.f);
}
__device__ __forceinline__ void mbar_wait_parity(uint32_t addr, uint32_t ph) {
    uint32_t done;
    asm volatile("{\n\t.reg .pred p;\n\t"
                 "mbarrier.try_wait.parity.acquire.cta.shared::cta.b64 p, [%1], %2;\n\t"
                 "selp.b32 %0, 1, 0, p;\n\t}"
                 : "=r"(done) : "r"(addr), "r"(ph) : "memory");
    if (!done) {
        asm volatile("{\n\t.reg .pred P1;\n\t"
                     "WL_%=:\n\t"
                     "mbarrier.try_wait.parity.acquire.cta.shared::cta.b64 P1, [%0], %1, 0x989680;\n\t"
                     "@P1 bra.uni WD_%=;\n\t"
                     "bra.uni WL_%=;\n\t"
                     "WD_%=:\n\t}"
                     :: "r"(addr), "r"(ph) : "memory");
    }
}

// smem float layout
#define SM_MB    0        // 4 floats = 2 x u64 mbarriers (16B), monolithic [parity]
#define SM_HB    4        // 2048 : 2 par x 4 col x 256 k
#define SM_XCH   2052     // 512 : 8 warps x 16 rows x 4 cols  (per-warp gate exchange)
#define SM_WZ    2564     // 256
#define SM_ZB    2820     // 64 ints of z bits
#define SM_SCR   2884     // 12 ints compaction scratch
#define SM_FLOATS 2896
#define LSTM_SMEM_BYTES (SM_FLOATS * 4)

__global__ void __launch_bounds__(256, 1) __cluster_dims__(8, 1, 1)
lstm_kernel(const int* __restrict__ sentences, const float* __restrict__ noise,
            const float* __restrict__ W_hh, const float* __restrict__ b_ih,
            const float* __restrict__ b_hh,
            const float* __restrict__ W_z, const float* __restrict__ b_z_p,
            float* __restrict__ out) {
    extern __shared__ float sm[];
    float* sm_hbuf  = sm + SM_HB;
    float* sm_xch   = sm + SM_XCH;
    float* sm_Wz    = sm + SM_WZ;
    int*   sm_zbits = (int*)(sm + SM_ZB);

    int tid = threadIdx.x;
    uint32_t r;
    asm("mov.u32 %0, %%cluster_ctarank;" : "=r"(r));
    int cid   = blockIdx.x >> 3;
    int colg0 = cid * 4;
    int lane = tid & 31;
    int w    = tid >> 5;
    int kh   = lane >> 4;             // K-half within warp
    int rl   = lane & 15;             // local row 0..15
    int rowp = w * 16 + rl;           // row' = q_local*4 + g
    int ql   = rowp >> 2;             // unit 0..31
    int gg_  = rowp & 3;              // gate 0..3

    // register-resident weights: row' -> original j = g*256 + r*32 + q
    ull wp[64];
    {
        int j = gg_ * 256 + (int)r * 32 + ql;
        const float2* wsrc = (const float2*)(W_hh + j * 256 + kh * 128);
#pragma unroll
        for (int i = 0; i < 64; i++) {
            float2 ww = wsrc[i];
            wp[i] = pack2(ww.x, ww.y);
        }
    }

    sm_Wz[tid] = W_z[tid & 255];
    for (int idx = tid; idx < 2048; idx += 256) sm_hbuf[idx] = 0.f;
    for (int idx = tid; idx < 64; idx += 256) sm_zbits[idx] = 0;

    // mbarriers: monolithic per parity slot; pre-arm both (4096 tx bytes)
    uint32_t mb_local = (uint32_t)__cvta_generic_to_shared(sm + SM_MB);
    if (tid == 0) {
        asm volatile("mbarrier.init.shared.b64 [%0], 1;" :: "r"(mb_local)     : "memory");
        asm volatile("mbarrier.init.shared.b64 [%0], 1;" :: "r"(mb_local + 8) : "memory");
        asm volatile("mbarrier.arrive.expect_tx.shared.b64 _, [%0], 4096;" :: "r"(mb_local)     : "memory");
        asm volatile("mbarrier.arrive.expect_tx.shared.b64 _, [%0], 4096;" :: "r"(mb_local + 8) : "memory");
    }

    // pointwise constants: lane<16 handles (unit q = w*4 + (lane>>2), col = lane&3)
    int pq = w * 4 + (lane >> 2);
    int pc = lane & 3;
    float b0 = 0.f, b1 = 0.f, b2 = 0.f, b3 = 0.f, creg = 0.f;
    if (lane < 16) {
        int jb0 = (int)r * 32 + pq;
        b0 = b_ih[jb0]       + b_hh[jb0];
        b1 = b_ih[jb0 + 256] + b_hh[jb0 + 256];
        b2 = b_ih[jb0 + 512] + b_hh[jb0 + 512];
        b3 = b_ih[jb0 + 768] + b_hh[jb0 + 768];
    }
    float bz = b_z_p[0];
    __syncthreads();

    // peer addresses for hbuf and mbarriers
    uint32_t hb_local = (uint32_t)__cvta_generic_to_shared(sm_hbuf);
    uint32_t peer_hb[8], peer_mb[8];
#pragma unroll
    for (int p = 0; p < 8; p++) {
        asm("mapa.shared::cluster.u32 %0, %1, %2;" : "=r"(peer_hb[p]) : "r"(hb_local), "r"(p));
        asm("mapa.shared::cluster.u32 %0, %1, %2;" : "=r"(peer_mb[p]) : "r"(mb_local), "r"(p));
    }

    // token prefetch register (pointwise lanes): token for t=0
    int tokC = 0;
    if (lane < 16) tokC = sentences[colg0 + pc];

    float nz = 0.f;
    uint32_t ph0 = 0, ph1 = 0;
    uint32_t zchunk = 0;
    cluster_sync_();                 // all mbarriers initialized cluster-wide

    for (int t = 0; t < T_STEPS; t++) {
        int par  = t & 1;
        int wpar = par ^ 1;

        // ---- x-gate loads + next-token prefetch (pointwise lanes) ----
        float xg0 = 0.f, xg1 = 0.f, xg2 = 0.f, xg3 = 0.f;
        int tokN = 0;
        if (lane < 16) {
            const float* Pp = d_P + (size_t)tokC * G4 + (int)r * 128 + pq;
            xg0 = Pp[0]; xg1 = Pp[32]; xg2 = Pp[64]; xg3 = Pp[96];
            int tn = (t + 1 < T_STEPS) ? t + 1 : T_STEPS - 1;
            tokN = sentences[tn * BATCH + colg0 + pc];
        }

        // ---- matmul: (row', K-half) x 4 cols, weights in registers ----
        ull aA0 = 0ull, aB0 = 0ull, aA1 = 0ull, aB1 = 0ull;
        ull aA2 = 0ull, aB2 = 0ull, aA3 = 0ull, aB3 = 0ull;
        {
            const ulonglong2* hp0 = (const ulonglong2*)(sm_hbuf + par * 1024 + 0 * 256 + kh * 128);
            const ulonglong2* hp1 = (const ulonglong2*)(sm_hbuf + par * 1024 + 1 * 256 + kh * 128);
            const ulonglong2* hp2 = (const ulonglong2*)(sm_hbuf + par * 1024 + 2 * 256 + kh * 128);
            const ulonglong2* hp3 = (const ulonglong2*)(sm_hbuf + par * 1024 + 3 * 256 + kh * 128);
#pragma unroll
            for (int i = 0; i < 32; i++) {
                ulonglong2 h0 = hp0[i];
                fma2(aA0, wp[2 * i], h0.x); fma2(aB0, wp[2 * i + 1], h0.y);
                ulonglong2 h1 = hp1[i];
                fma2(aA1, wp[2 * i], h1.x); fma2(aB1, wp[2 * i + 1], h1.y);
                ulonglong2 h2 = hp2[i];
                fma2(aA2, wp[2 * i], h2.x); fma2(aB2, wp[2 * i + 1], h2.y);
                ulonglong2 h3 = hp3[i];
                fma2(aA3, wp[2 * i], h3.x); fma2(aB3, wp[2 * i + 1], h3.y);
            }
        }
        float s0, s1, s2, s3;
        {
            F2 xa, xb;
            xa.u = aA0; xb.u = aB0; s0 = (xa.f.x + xa.f.y) + (xb.f.x + xb.f.y);
            xa.u = aA1; xb.u = aB1; s1 = (xa.f.x + xa.f.y) + (xb.f.x + xb.f.y);
            xa.u = aA2; xb.u = aB2; s2 = (xa.f.x + xa.f.y) + (xb.f.x + xb.f.y);
            xa.u = aA3; xb.u = aB3; s3 = (xa.f.x + xa.f.y) + (xb.f.x + xb.f.y);
        }
        // combine K-halves within warp (lanes L and L^16 share row')
        s0 += __shfl_xor_sync(0xffffffffu, s0, 16);
        s1 += __shfl_xor_sync(0xffffffffu, s1, 16);
        s2 += __shfl_xor_sync(0xffffffffu, s2, 16);
        s3 += __shfl_xor_sync(0xffffffffu, s3, 16);
        if (lane < 16)
            ((float4*)sm_xch)[w * 16 + rl] = make_float4(s0, s1, s2, s3);
        __syncwarp();

        if (lane < 16) {
            // gather 4 gates of unit pq at col pc from the warp patch
            int a4 = (lane >> 2) * 4;
            float gi = sm_xch[w * 64 + (a4 + 0) * 4 + pc] + xg0 + b0;
            float gf = sm_xch[w * 64 + (a4 + 1) * 4 + pc] + xg1 + b1;
            float gv = sm_xch[w * 64 + (a4 + 2) * 4 + pc] + xg2 + b2;
            float go = sm_xch[w * 64 + (a4 + 3) * 4 + pc] + xg3 + b3;
            creg = sigf(gf) * creg + sigf(gi) * tanhfast(gv);
            float h = sigf(go) * tanhfast(creg);
            tokC = tokN;
            uint32_t off  = (uint32_t)(((wpar * 1024) + pc * 256 + (int)r * 32 + pq) * 4);
            uint32_t moff = (uint32_t)(wpar * 8);
#pragma unroll
            for (int p8 = 0; p8 < 8; p8++)
                asm volatile("st.async.shared::cluster.mbarrier::complete_tx::bytes.f32 [%0], %1, [%2];"
                             :: "r"(peer_hb[p8] + off), "f"(h), "r"(peer_mb[p8] + moff) : "memory");
        }

        // ---- pz/z for output t-1: warp 7 after its ships (R12-proven margin) ----
        if (w == 7 && (int)r < 4) {
            if (t > 0) {
                float acc = 0.f;
                const float* hrow = sm_hbuf + par * 1024 + (int)r * 256;
#pragma unroll
                for (int jj = 0; jj < 8; jj++)
                    acc += hrow[lane + jj * 32] * sm_Wz[lane + jj * 32];
#pragma unroll
                for (int off = 16; off; off >>= 1)
                    acc += __shfl_down_sync(0xffffffffu, acc, off);
                if (lane == 0) {
                    float pz = sigf(acc + bz);
                    int oi = t - 1;
                    int o = oi * BATCH + colg0 + (int)r;
                    uint32_t zb = (nz < pz) ? 1u : 0u;
                    out[o]        = pz;
                    out[TBsz + o] = (float)zb;
                    zchunk |= zb << (oi & 31);
                    if ((oi & 31) == 31) { sm_zbits[oi >> 5] = (int)zchunk; zchunk = 0; }
                }
            }
            if (lane == 0) nz = noise[t * BATCH + colg0 + (int)r];
        }

        // ---- monolithic wait for all 8 CTAs' h (4096 tx bytes), then re-arm ----
        if (wpar == 0) { mbar_wait_parity(mb_local,     ph0); ph0 ^= 1; }
        else           { mbar_wait_parity(mb_local + 8, ph1); ph1 ^= 1; }
        if (tid == 0)
            asm volatile("mbarrier.arrive.expect_tx.shared.b64 _, [%0], 4096;"
                         :: "r"(mb_local + (uint32_t)(wpar * 8)) : "memory");
    }

    // final pz for t_out = 2047 (h_2047 in parity 0; acquired by final monolithic wait)
    if ((int)r < 4 && w == 7) {
        float acc = 0.f;
        const float* hrow = sm_hbuf + (int)r * 256;
#pragma unroll
        for (int off2 = 0; off2 < 8; off2++)
            acc += hrow[lane + off2 * 32] * sm_Wz[lane + off2 * 32];
#pragma unroll
        for (int off = 16; off; off >>= 1)
            acc += __shfl_down_sync(0xffffffffu, acc, off);
        if (lane == 0) {
            float pz = sigf(acc + bz);
            int o = 2047 * BATCH + colg0 + (int)r;
            uint32_t zb = (nz < pz) ? 1u : 0u;
            out[o]        = pz;
            out[TBsz + o] = (float)zb;
            zchunk |= zb << 31;
            sm_zbits[63] = (int)zchunk;
        }
    }
    cluster_sync_();   // no CTA exits while peers' async stores may still target it
    __syncthreads();

    // ---- fused per-column compaction (CTA r<4 handles column colg0+r) ----
    {
        int b = colg0 + (int)r;
        int* wsum = (int*)(sm + SM_SCR);
        int* s_total = wsum + 8;

        uint32_t byte = ((uint32_t)sm_zbits[tid >> 2] >> ((tid & 3) * 8)) & 0xFFu;
        int cnt = __popc(byte);
        int x = cnt;
#pragma unroll
        for (int off = 1; off < 32; off <<= 1) {
            int y = __shfl_up_sync(0xffffffffu, x, off);
            if (lane >= off) x += y;
        }
        if (lane == 31) wsum[w] = x;
        __syncthreads();
        if (tid == 0) {
            int s = 0;
            for (int k = 0; k < 8; k++) { int v = wsum[k]; wsum[k] = s; s += v; }
            *s_total = s;
        }
        __syncthreads();
        if ((int)r < 4) {
            int base = wsum[w] + (x - cnt);
            int t0 = tid * 8;
            int pos = base;
#pragma unroll
            for (int k = 0; k < 8; k++) {
                if ((byte >> k) & 1u) {
                    out[2 * TBsz + pos * BATCH + b] = (float)sentences[(t0 + k) * BATCH + b];
                    pos++;
                }
            }
            int total = *s_total;
            for (int p = total + tid; p < T_STEPS; p += 256)
                out[2 * TBsz + p * BATCH + b] = 0.0f;   // PAD_ID = 0
            if (tid == 0) out[3 * TBsz + b] = (float)total;
        }
    }
}

// ---------------- launch ----------------
extern "C" void kernel_launch(void* const* d_in, const int* in_sizes, int n_in,
                              void* d_out, int out_size) {
    const int*   sentences = (const int*)  d_in[0];
    const float* noise     = (const float*)d_in[1];
    const float* emb       = (const float*)d_in[2];
    const float* W_ih      = (const float*)d_in[3];
    const float* W_hh      = (const float*)d_in[4];
    const float* b_ih      = (const float*)d_in[5];
    const float* b_hh      = (const float*)d_in[6];
    const float* W_z       = (const float*)d_in[7];
    const float* b_z       = (const float*)d_in[8];
    float* out = (float*)d_out;

    cudaFuncSetAttribute(lstm_kernel, cudaFuncAttributeMaxDynamicSharedMemorySize,
                         LSTM_SMEM_BYTES);

    proj_kernel<<<dim3((VOCAB + BM - 1) / BM, G4 / BN), 256>>>(emb, W_ih);
    lstm_kernel<<<128, 256, LSTM_SMEM_BYTES>>>(sentences, noise, W_hh, b_ih, b_hh,
                                               W_z, b_z, out);
}

// round 15
// speedup vs baseline: 1.5447x; 1.5447x over previous
#include <cuda_runtime.h>
#include <cuda_bf16.h>
#include <cstdint>
#include <math.h>

#define T_STEPS 2048
#define BATCH   64
#define EDIM    256
#define HDIM    256
#define G4      1024
#define VOCAB   50257
#define TBsz    (T_STEPS*BATCH)

typedef unsigned long long ull;

// ---------------- device scratch (no cudaMalloc allowed) ----------------
__device__ float d_P[(size_t)VOCAB * G4];   // projected embedding table (UNpermuted)

__device__ __forceinline__ ull pack2(float a, float b) {
    ull r; asm("mov.b64 %0, {%1, %2};" : "=l"(r) : "f"(a), "f"(b)); return r;
}
__device__ __forceinline__ void fma2(ull& d, ull a, ull b) {
    asm("fma.rn.f32x2 %0, %1, %2, %0;" : "+l"(d) : "l"(a), "l"(b));
}
union F2 { ull u; float2 f; };

// ---------------- kernel 1: P = emb @ W_ih^T (NT gemm), f32x2 ----------------
#define BM 128
#define BN 128
#define BK 32
__global__ void __launch_bounds__(256)
proj_kernel(const float* __restrict__ emb, const float* __restrict__ Wih) {
    __shared__ float As[BK][BM + 1];
    __shared__ float Bs[BK][BN + 1];
    int l  = threadIdx.x;
    int v0 = blockIdx.x * BM;
    int j0 = blockIdx.y * BN;
    int ty = l >> 4, tx = l & 15;

    ull acc2[8][4];
#pragma unroll
    for (int i = 0; i < 8; i++)
#pragma unroll
        for (int j = 0; j < 4; j++) acc2[i][j] = 0ull;

    for (int kt = 0; kt < EDIM; kt += BK) {
        for (int idx = l; idx < BM * BK; idx += 256) {
            int vr = idx >> 5; int e = idx & 31;
            int v = v0 + vr;
            As[e][vr] = (v < VOCAB) ? emb[v * EDIM + kt + e] : 0.f;
        }
        for (int idx = l; idx < BN * BK; idx += 256) {
            int jr = idx >> 5; int e = idx & 31;
            Bs[e][jr] = Wih[(j0 + jr) * EDIM + kt + e];
        }
        __syncthreads();
#pragma unroll
        for (int kk = 0; kk < BK; kk++) {
            float a[8], b[8];
#pragma unroll
            for (int i = 0; i < 8; i++) a[i] = As[kk][ty * 8 + i];
#pragma unroll
            for (int i = 0; i < 8; i++) b[i] = Bs[kk][tx * 8 + i];
            ull pa[8], pb[4];
#pragma unroll
            for (int i = 0; i < 8; i++) pa[i] = pack2(a[i], a[i]);
#pragma unroll
            for (int j = 0; j < 4; j++) pb[j] = pack2(b[2 * j], b[2 * j + 1]);
#pragma unroll
            for (int i = 0; i < 8; i++)
#pragma unroll
                for (int j = 0; j < 4; j++) fma2(acc2[i][j], pa[i], pb[j]);
        }
        __syncthreads();
    }
    int pj0 = j0 + tx * 8;           // no permutation
#pragma unroll
    for (int i = 0; i < 8; i++) {
        int v = v0 + ty * 8 + i;
        if (v < VOCAB) {
#pragma unroll
            for (int j = 0; j < 4; j++) {
                F2 x; x.u = acc2[i][j];
                d_P[(size_t)v * G4 + pj0 + 2 * j]     = x.f.x;
                d_P[(size_t)v * G4 + pj0 + 2 * j + 1] = x.f.y;
            }
        }
    }
}

// ---------------- kernel 2: persistent 4-CTA-cluster LSTM + fused compaction ----------------
__device__ __forceinline__ void cluster_sync_() {
    asm volatile("barrier.cluster.arrive.aligned;" ::: "memory");
    asm volatile("barrier.cluster.wait.aligned;" ::: "memory");
}
__device__ __forceinline__ float sigf(float x) {
    return __fdividef(1.f, 1.f + __expf(-x));
}
__device__ __forceinline__ float tanhfast(float x) {
    return 1.f - 2.f * __fdividef(1.f, __expf(2.f * x) + 1.f);
}
__device__ __forceinline__ void mbar_wait_parity(uint32_t addr, uint32_t ph) {
    uint32_t done;
    asm volatile("{\n\t.reg .pred p;\n\t"
                 "mbarrier.try_wait.parity.acquire.cta.shared::cta.b64 p, [%1], %2;\n\t"
                 "selp.b32 %0, 1, 0, p;\n\t}"
                 : "=r"(done) : "r"(addr), "r"(ph) : "memory");
    if (!done) {
        asm volatile("{\n\t.reg .pred P1;\n\t"
                     "WL_%=:\n\t"
                     "mbarrier.try_wait.parity.acquire.cta.shared::cta.b64 P1, [%0], %1, 0x989680;\n\t"
                     "@P1 bra.uni WD_%=;\n\t"
                     "bra.uni WL_%=;\n\t"
                     "WD_%=:\n\t}"
                     :: "r"(addr), "r"(ph) : "memory");
    }
}

#define WSTRIDE 132   // 128 weights + 4 pad (conflict-free LDS.128)

// smem float layout
#define SM_MB    0        // 4 floats = 2 x u64 mbarriers (monolithic per parity)
#define SM_HB    4        // 1024 : 2 par x 2 col x 256 k
#define SM_XCH   1028     // 512  : 8 warps x 32 rows x 2 cols
#define SM_WZ    1540     // 256
#define SM_ZB    1796     // 64 ints of z bits
#define SM_SCR   1860     // 12 ints compaction scratch
#define SM_W     1872     // 256 rows x 132 = 33792 (weights k=128..255)
#define SM_FLOATS (SM_W + 256 * WSTRIDE)
#define LSTM_SMEM_BYTES (SM_FLOATS * 4)

__global__ void __launch_bounds__(256, 1) __cluster_dims__(4, 1, 1)
lstm_kernel(const int* __restrict__ sentences, const float* __restrict__ noise,
            const float* __restrict__ W_hh, const float* __restrict__ b_ih,
            const float* __restrict__ b_hh,
            const float* __restrict__ W_z, const float* __restrict__ b_z_p,
            float* __restrict__ out) {
    extern __shared__ float sm[];
    float* sm_hbuf  = sm + SM_HB;
    float* sm_xch   = sm + SM_XCH;
    float* sm_Wz    = sm + SM_WZ;
    int*   sm_zbits = (int*)(sm + SM_ZB);
    float* sm_W     = sm + SM_W;

    int tid = threadIdx.x;
    uint32_t r;
    asm("mov.u32 %0, %%cluster_ctarank;" : "=r"(r));
    int cid   = blockIdx.x >> 2;      // 32 clusters of 4 CTAs
    int colg0 = cid * 2;              // 2 batch columns per cluster
    int lane = tid & 31;
    int w    = tid >> 5;
    int q    = tid >> 2;              // unit 0..63 (this CTA's slice)
    int g    = tid & 3;               // gate 0..3
    int j    = g * 256 + (int)r * 64 + q;   // original gate-row in W_hh

    // weights: k<128 in registers (64 ull pairs); k>=128 staged to smem
    ull wp[64];
    {
        const float2* wsrc = (const float2*)(W_hh + (size_t)j * 256);
#pragma unroll
        for (int i = 0; i < 64; i++) {
            float2 ww = wsrc[i];
            wp[i] = pack2(ww.x, ww.y);
        }
        const float* wh = W_hh + (size_t)j * 256 + 128;
#pragma unroll 8
        for (int kk = 0; kk < 128; kk++)
            sm_W[tid * WSTRIDE + kk] = wh[kk];
    }

    sm_Wz[tid] = W_z[tid & 255];
    for (int idx = tid; idx < 1024; idx += 256) sm_hbuf[idx] = 0.f;
    for (int idx = tid; idx < 64; idx += 256) sm_zbits[idx] = 0;

    // monolithic mbarriers per parity; pre-arm 2048 tx bytes (4 CTAs x 512B)
    uint32_t mb_local = (uint32_t)__cvta_generic_to_shared(sm + SM_MB);
    if (tid == 0) {
        asm volatile("mbarrier.init.shared.b64 [%0], 1;" :: "r"(mb_local)     : "memory");
        asm volatile("mbarrier.init.shared.b64 [%0], 1;" :: "r"(mb_local + 8) : "memory");
        asm volatile("mbarrier.arrive.expect_tx.shared.b64 _, [%0], 2048;" :: "r"(mb_local)     : "memory");
        asm volatile("mbarrier.arrive.expect_tx.shared.b64 _, [%0], 2048;" :: "r"(mb_local + 8) : "memory");
    }

    // pointwise lanes: lane<16 of warp w handles (unit pu = w*8 + (lane>>1), col pc = lane&1)
    int pu = w * 8 + (lane >> 1);
    int pc = lane & 1;
    float b0 = 0.f, b1 = 0.f, b2 = 0.f, b3 = 0.f, creg = 0.f;
    int tokC = 0;
    if (lane < 16) {
        int jb0 = (int)r * 64 + pu;
        b0 = b_ih[jb0]       + b_hh[jb0];
        b1 = b_ih[jb0 + 256] + b_hh[jb0 + 256];
        b2 = b_ih[jb0 + 512] + b_hh[jb0 + 512];
        b3 = b_ih[jb0 + 768] + b_hh[jb0 + 768];
        tokC = sentences[colg0 + pc];
    }
    float bz = b_z_p[0];
    __syncthreads();

    // peer addresses (4 CTAs)
    uint32_t hb_local = (uint32_t)__cvta_generic_to_shared(sm_hbuf);
    uint32_t peer_hb[4], peer_mb[4];
#pragma unroll
    for (int p = 0; p < 4; p++) {
        asm("mapa.shared::cluster.u32 %0, %1, %2;" : "=r"(peer_hb[p]) : "r"(hb_local), "r"(p));
        asm("mapa.shared::cluster.u32 %0, %1, %2;" : "=r"(peer_mb[p]) : "r"(mb_local), "r"(p));
    }

    float nz = 0.f;
    uint32_t ph0 = 0, ph1 = 0;
    uint32_t zchunk = 0;
    cluster_sync_();                 // all mbarriers initialized cluster-wide

    for (int t = 0; t < T_STEPS; t++) {
        int par  = t & 1;
        int wpar = par ^ 1;

        // ---- x-gate loads + next-token prefetch (pointwise lanes) ----
        float xg0 = 0.f, xg1 = 0.f, xg2 = 0.f, xg3 = 0.f;
        int tokN = 0;
        if (lane < 16) {
            const float* Pp = d_P + (size_t)tokC * G4 + (int)r * 64 + pu;
            xg0 = Pp[0]; xg1 = Pp[256]; xg2 = Pp[512]; xg3 = Pp[768];
            int tn = (t + 1 < T_STEPS) ? t + 1 : T_STEPS - 1;
            tokN = sentences[tn * BATCH + colg0 + pc];
        }

        // ---- matmul: row j x 2 cols, k<128 from regs, k>=128 from smem ----
        ull a0A = 0ull, a0B = 0ull, a1A = 0ull, a1B = 0ull;
        {
            const ulonglong2* h0 = (const ulonglong2*)(sm_hbuf + par * 512);
            const ulonglong2* h1 = (const ulonglong2*)(sm_hbuf + par * 512 + 256);
#pragma unroll
            for (int i = 0; i < 32; i++) {
                ulonglong2 ha = h0[i];
                fma2(a0A, wp[2 * i], ha.x); fma2(a0B, wp[2 * i + 1], ha.y);
                ulonglong2 hb = h1[i];
                fma2(a1A, wp[2 * i], hb.x); fma2(a1B, wp[2 * i + 1], hb.y);
            }
            const ulonglong2* ws = (const ulonglong2*)(sm_W + tid * WSTRIDE);
#pragma unroll
            for (int i = 0; i < 32; i++) {
                ulonglong2 wv = ws[i];
                ulonglong2 ha = h0[32 + i];
                fma2(a0A, wv.x, ha.x); fma2(a0B, wv.y, ha.y);
                ulonglong2 hb = h1[32 + i];
                fma2(a1A, wv.x, hb.x); fma2(a1B, wv.y, hb.y);
            }
        }
        {
            F2 xa, xb;
            float s0, s1;
            xa.u = a0A; xb.u = a0B; s0 = (xa.f.x + xa.f.y) + (xb.f.x + xb.f.y);
            xa.u = a1A; xb.u = a1B; s1 = (xa.f.x + xa.f.y) + (xb.f.x + xb.f.y);
            ((float2*)sm_xch)[w * 32 + (tid & 31)] = make_float2(s0, s1);
        }
        __syncwarp();

        if (lane < 16) {
            // gather 4 gates of unit pu at col pc (warp-local rows 4*lpu..4*lpu+3)
            const float* X = sm_xch + w * 64;
            int a4 = (lane >> 1) * 4;
            float gi = X[(a4 + 0) * 2 + pc] + xg0 + b0;
            float gf = X[(a4 + 1) * 2 + pc] + xg1 + b1;
            float gv = X[(a4 + 2) * 2 + pc] + xg2 + b2;
            float go = X[(a4 + 3) * 2 + pc] + xg3 + b3;
            creg = sigf(gf) * creg + sigf(gi) * tanhfast(gv);
            float h = sigf(go) * tanhfast(creg);
            tokC = tokN;
            uint32_t off  = (uint32_t)(((wpar * 512) + pc * 256 + (int)r * 64 + pu) * 4);
            uint32_t moff = (uint32_t)(wpar * 8);
#pragma unroll
            for (int p4 = 0; p4 < 4; p4++)
                asm volatile("st.async.shared::cluster.mbarrier::complete_tx::bytes.f32 [%0], %1, [%2];"
                             :: "r"(peer_hb[p4] + off), "f"(h), "r"(peer_mb[p4] + moff) : "memory");
        } else if (w == 6 && (int)r < 2) {
            // ---- pz/z for output t-1 on warp 6 upper lanes (16..31), col colg0+r ----
            // hbuf[par] fully acquired by this thread at end of step t-1 (monolithic).
            int l16 = lane - 16;
            if (t > 0) {
                float acc = 0.f;
                const float* hrow = sm_hbuf + par * 512 + (int)r * 256;
#pragma unroll
                for (int jj = 0; jj < 16; jj++)
                    acc += hrow[l16 + jj * 16] * sm_Wz[l16 + jj * 16];
#pragma unroll
                for (int off = 8; off; off >>= 1)
                    acc += __shfl_down_sync(0xFFFF0000u, acc, off);
                if (l16 == 0) {
                    float pz = sigf(acc + bz);
                    int oi = t - 1;
                    int o = oi * BATCH + colg0 + (int)r;
                    uint32_t zb = (nz < pz) ? 1u : 0u;
                    out[o]        = pz;
                    out[TBsz + o] = (float)zb;
                    zchunk |= zb << (oi & 31);
                    if ((oi & 31) == 31) { sm_zbits[oi >> 5] = (int)zchunk; zchunk = 0; }
                }
            }
            if (l16 == 0) nz = noise[t * BATCH + colg0 + (int)r];
        }

        // ---- monolithic wait for all 4 CTAs' h (2048 tx bytes), then re-arm ----
        if (wpar == 0) { mbar_wait_parity(mb_local,     ph0); ph0 ^= 1; }
        else           { mbar_wait_parity(mb_local + 8, ph1); ph1 ^= 1; }
        if (tid == 0)
            asm volatile("mbarrier.arrive.expect_tx.shared.b64 _, [%0], 2048;"
                         :: "r"(mb_local + (uint32_t)(wpar * 8)) : "memory");
    }

    // final pz for t_out = 2047 (h_2047 in parity 0; acquired by final wait)
    if ((int)r < 2 && w == 6 && lane >= 16) {
        int l16 = lane - 16;
        float acc = 0.f;
        const float* hrow = sm_hbuf + (int)r * 256;
#pragma unroll
        for (int jj = 0; jj < 16; jj++)
            acc += hrow[l16 + jj * 16] * sm_Wz[l16 + jj * 16];
#pragma unroll
        for (int off = 8; off; off >>= 1)
            acc += __shfl_down_sync(0xFFFF0000u, acc, off);
        if (l16 == 0) {
            float pz = sigf(acc + bz);
            int o = 2047 * BATCH + colg0 + (int)r;
            uint32_t zb = (nz < pz) ? 1u : 0u;
            out[o]        = pz;
            out[TBsz + o] = (float)zb;
            zchunk |= zb << 31;
            sm_zbits[63] = (int)zchunk;
        }
    }
    cluster_sync_();   // no CTA exits while peers' async stores may still target it
    __syncthreads();

    // ---- fused per-column compaction (CTA r<2 handles column colg0+r) ----
    {
        int b = colg0 + (int)r;
        int* wsum = (int*)(sm + SM_SCR);
        int* s_total = wsum + 8;

        uint32_t byte = ((uint32_t)sm_zbits[tid >> 2] >> ((tid & 3) * 8)) & 0xFFu;
        int cnt = __popc(byte);
        int x = cnt;
#pragma unroll
        for (int off = 1; off < 32; off <<= 1) {
            int y = __shfl_up_sync(0xffffffffu, x, off);
            if (lane >= off) x += y;
        }
        if (lane == 31) wsum[w] = x;
        __syncthreads();
        if (tid == 0) {
            int s = 0;
            for (int k = 0; k < 8; k++) { int v = wsum[k]; wsum[k] = s; s += v; }
            *s_total = s;
        }
        __syncthreads();
        if ((int)r < 2) {
            int base = wsum[w] + (x - cnt);
            int t0 = tid * 8;
            int pos = base;
#pragma unroll
            for (int k = 0; k < 8; k++) {
                if ((byte >> k) & 1u) {
                    out[2 * TBsz + pos * BATCH + b] = (float)sentences[(t0 + k) * BATCH + b];
                    pos++;
                }
            }
            int total = *s_total;
            for (int p = total + tid; p < T_STEPS; p += 256)
                out[2 * TBsz + p * BATCH + b] = 0.0f;   // PAD_ID = 0
            if (tid == 0) out[3 * TBsz + b] = (float)total;
        }
    }
}

// ---------------- launch ----------------
extern "C" void kernel_launch(void* const* d_in, const int* in_sizes, int n_in,
                              void* d_out, int out_size) {
    const int*   sentences = (const int*)  d_in[0];
    const float* noise     = (const float*)d_in[1];
    const float* emb       = (const float*)d_in[2];
    const float* W_ih      = (const float*)d_in[3];
    const float* W_hh      = (const float*)d_in[4];
    const float* b_ih      = (const float*)d_in[5];
    const float* b_hh      = (const float*)d_in[6];
    const float* W_z       = (const float*)d_in[7];
    const float* b_z       = (const float*)d_in[8];
    float* out = (float*)d_out;

    cudaFuncSetAttribute(lstm_kernel, cudaFuncAttributeMaxDynamicSharedMemorySize,
                         LSTM_SMEM_BYTES);

    proj_kernel<<<dim3((VOCAB + BM - 1) / BM, G4 / BN), 256>>>(emb, W_ih);
    lstm_kernel<<<128, 256, LSTM_SMEM_BYTES>>>(sentences, noise, W_hh, b_ih, b_hh,
                                               W_z, b_z, out);
}